// round 6
// baseline (speedup 1.0000x reference)
#include <cuda_runtime.h>

#define T_LEN 1024
#define B_SZ  32
#define H_SZ  8
#define D_SZ  32
#define YD_SZ 97
#define IN_SZ 256
#define NCOL  165     // 32 (Wq) + 32 (Wk) + 97 (Wy) + 4 (wb)
#define NTHREADS 224  // 7 warps

// FWM per-step outputs (T,B,H*D) = (T*B, 256) row-major
__device__ float g_scratch[T_LEN * B_SZ * IN_SZ];

// No-max softmax: mathematically identical (shift-invariance), and the raw
// pre-activations here are O(1) (dot of a probability vector with small
// weight columns), so exp cannot overflow. fminf(.,80) is a NaN-guard only.
// This halves the dependent SHFL chain vs the max+sum version.
__device__ __forceinline__ float warp_softmax32(float v) {
    float e = __expf(fminf(v, 80.0f));
    float s = e;
#pragma unroll
    for (int o = 16; o > 0; o >>= 1)
        s += __shfl_xor_sync(0xffffffffu, s, o);
    return __fdividef(e, s);
}

__global__ __launch_bounds__(NTHREADS)
void srwm_scan_kernel(const float* __restrict__ h_in,
                      const float* __restrict__ W_y,
                      const float* __restrict__ W_q,
                      const float* __restrict__ W_k,
                      const float* __restrict__ w_b,
                      const float* __restrict__ sWy,
                      const float* __restrict__ sWq,
                      const float* __restrict__ sWk,
                      const float* __restrict__ swb,
                      const float* __restrict__ Fw)
{
    const int bh   = blockIdx.x;      // 256 chains
    const int b    = bh >> 3;         // 0..31
    const int hh   = bh & 7;          // 0..7
    const int tid  = threadIdx.x;
    const int wid  = tid >> 5;
    const int lane = tid & 31;

    // Double-buffered inter-warp vectors (parity = t & 1).
    __shared__ float xbuf[2][D_SZ];
    __shared__ float qsh[2][D_SZ], ksh[2][D_SZ];
    __shared__ float fqsh[2][D_SZ], fksh[2][D_SZ], fvsh[2][D_SZ];
    __shared__ float betash[2][4];
    __shared__ float fbsh[2];

    // State column lives in registers for the whole scan.
    float col[D_SZ];

    // ---- init state columns: weights + initial state ----
    if (tid < 32) {
#pragma unroll
        for (int d = 0; d < D_SZ; d++)
            col[d] = W_q[(hh * D_SZ + d) * D_SZ + tid]
                   + sWq[(((b * H_SZ + hh) * D_SZ) + d) * D_SZ + tid];
    } else if (tid < 64) {
        const int j = tid - 32;
#pragma unroll
        for (int d = 0; d < D_SZ; d++)
            col[d] = W_k[(hh * D_SZ + d) * D_SZ + j]
                   + sWk[(((b * H_SZ + hh) * D_SZ) + d) * D_SZ + j];
    } else if (tid < 161) {
        const int j = tid - 64;
#pragma unroll
        for (int d = 0; d < D_SZ; d++)
            col[d] = W_y[(hh * D_SZ + d) * YD_SZ + j]
                   + sWy[(((b * H_SZ + hh) * D_SZ) + d) * YD_SZ + j];
    } else if (tid < NCOL) {
        const int j = tid - 161;
#pragma unroll
        for (int d = 0; d < D_SZ; d++)
            col[d] = w_b[(hh * D_SZ + d) * 4 + j]
                   + swb[(((b * H_SZ + hh) * D_SZ) + d) * 4 + j];
    } else if (wid == 6) {
        // fast-weight memory column
#pragma unroll
        for (int d = 0; d < D_SZ; d++)
            col[d] = Fw[(((b * H_SZ + hh) * D_SZ) + d) * D_SZ + lane];
    }

    // Warp 5 owns the x pipeline (its phase-1 is the shortest).
    float xreg = 0.f;
    const float* hbase = h_in + (size_t)b * IN_SZ + hh * D_SZ + lane;
    if (wid == 5) {
        xbuf[0][lane] = warp_softmax32(hbase[0]);
        xreg = hbase[(size_t)1 * B_SZ * IN_SZ];
    }
    float* scr_base = g_scratch + (size_t)b * IN_SZ + hh * D_SZ + lane;
    __syncthreads();

    for (int t = 0; t < T_LEN; ++t) {
        const int p = t & 1;
        const float4* x4 = reinterpret_cast<const float4*>(xbuf[p]);

        // ---- phase 1 ----
        if (wid < 5) {
            float a0 = 0.f, a1 = 0.f, a2 = 0.f, a3 = 0.f;
#pragma unroll
            for (int d4 = 0; d4 < 8; d4++) {
                float4 xv = x4[d4];
                a0 = fmaf(xv.x, col[4 * d4 + 0], a0);
                a1 = fmaf(xv.y, col[4 * d4 + 1], a1);
                a2 = fmaf(xv.z, col[4 * d4 + 2], a2);
                a3 = fmaf(xv.w, col[4 * d4 + 3], a3);
            }
            float raw = (a0 + a1) + (a2 + a3);
            if      (wid == 0) qsh[p][lane]  = warp_softmax32(raw);   // q
            else if (wid == 1) ksh[p][lane]  = warp_softmax32(raw);   // k
            else if (wid == 2) fqsh[p][lane] = warp_softmax32(raw);   // fq
            else if (wid == 3) fksh[p][lane] = warp_softmax32(raw);   // fk
            else               fvsh[p][lane] = raw;                   // fv
        } else if (wid == 5) {
            // lanes 0..4 own cols 160..164 (fb column of Wy + the 4 wb cols)
            if (lane < 5) {
                float a0 = 0.f, a1 = 0.f, a2 = 0.f, a3 = 0.f;
#pragma unroll
                for (int d4 = 0; d4 < 8; d4++) {
                    float4 xv = x4[d4];
                    a0 = fmaf(xv.x, col[4 * d4 + 0], a0);
                    a1 = fmaf(xv.y, col[4 * d4 + 1], a1);
                    a2 = fmaf(xv.z, col[4 * d4 + 2], a2);
                    a3 = fmaf(xv.w, col[4 * d4 + 3], a3);
                }
                float raw = (a0 + a1) + (a2 + a3);
                float sg = 1.0f / (1.0f + __expf(-raw));
                if (lane == 0) fbsh[p] = sg;                          // fb
                else           betash[p][lane - 1] = sg;              // beta
            }
            // full warp: x_{t+1} softmax + prefetch h[t+2]
            xbuf[p ^ 1][lane] = warp_softmax32(xreg);
            if (t + 2 < T_LEN)
                xreg = hbase[(size_t)(t + 2) * B_SZ * IN_SZ];
        } else if (t > 0) {   // wid == 6
            // FWM for step t-1 (reads parity p^1 buffers, written at t-1)
            const int pp = p ^ 1;
            const float4* fk4 = reinterpret_cast<const float4*>(fksh[pp]);
            const float4* fq4 = reinterpret_cast<const float4*>(fqsh[pp]);
            const float fbv = fbsh[pp];
            const float fvv = fvsh[pp][lane];
            float v0 = 0.f, v1 = 0.f;
#pragma unroll
            for (int d4 = 0; d4 < 8; d4++) {
                float4 kv = fk4[d4];
                v0 = fmaf(kv.x, col[4 * d4 + 0], v0);
                v1 = fmaf(kv.y, col[4 * d4 + 1], v1);
                v0 = fmaf(kv.z, col[4 * d4 + 2], v0);
                v1 = fmaf(kv.w, col[4 * d4 + 3], v1);
            }
            const float coeff = fbv * (fvv - (v0 + v1));
            float o0 = 0.f, o1 = 0.f, o2 = 0.f, o3 = 0.f;
#pragma unroll
            for (int d4 = 0; d4 < 8; d4++) {
                float4 kv = fk4[d4];
                float4 qv = fq4[d4];
                col[4 * d4 + 0] = fmaf(kv.x, coeff, col[4 * d4 + 0]);
                col[4 * d4 + 1] = fmaf(kv.y, coeff, col[4 * d4 + 1]);
                col[4 * d4 + 2] = fmaf(kv.z, coeff, col[4 * d4 + 2]);
                col[4 * d4 + 3] = fmaf(kv.w, coeff, col[4 * d4 + 3]);
                o0 = fmaf(qv.x, col[4 * d4 + 0], o0);
                o1 = fmaf(qv.y, col[4 * d4 + 1], o1);
                o2 = fmaf(qv.z, col[4 * d4 + 2], o2);
                o3 = fmaf(qv.w, col[4 * d4 + 3], o3);
            }
            scr_base[(size_t)(t - 1) * B_SZ * IN_SZ] = (o0 + o1) + (o2 + o3);
        }
        __syncthreads();   // the ONLY barrier per step

        // ---- phase 2: rank-1 SRWM updates (warps 0-5); no trailing barrier ----
        if (tid < NCOL) {
            const float bsel = betash[p][(tid < 32)  ? 1
                                        : (tid < 64)  ? 2
                                        : (tid < 161) ? 0
                                                      : 3];
            const float4* q4 = reinterpret_cast<const float4*>(qsh[p]);
            const float4* k4 = reinterpret_cast<const float4*>(ksh[p]);
            float vq0 = 0.f, vq1 = 0.f, vq2 = 0.f, vq3 = 0.f;
            float vk0 = 0.f, vk1 = 0.f, vk2 = 0.f, vk3 = 0.f;
#pragma unroll
            for (int d4 = 0; d4 < 8; d4++) {
                float4 qv = q4[d4];
                float4 kv = k4[d4];
                vq0 = fmaf(qv.x, col[4 * d4 + 0], vq0);
                vq1 = fmaf(qv.y, col[4 * d4 + 1], vq1);
                vq2 = fmaf(qv.z, col[4 * d4 + 2], vq2);
                vq3 = fmaf(qv.w, col[4 * d4 + 3], vq3);
                vk0 = fmaf(kv.x, col[4 * d4 + 0], vk0);
                vk1 = fmaf(kv.y, col[4 * d4 + 1], vk1);
                vk2 = fmaf(kv.z, col[4 * d4 + 2], vk2);
                vk3 = fmaf(kv.w, col[4 * d4 + 3], vk3);
            }
            const float diff = bsel * (((vq0 + vq1) + (vq2 + vq3))
                                     - ((vk0 + vk1) + (vk2 + vk3)));
#pragma unroll
            for (int d4 = 0; d4 < 8; d4++) {
                float4 kv = k4[d4];
                col[4 * d4 + 0] = fmaf(kv.x, diff, col[4 * d4 + 0]);
                col[4 * d4 + 1] = fmaf(kv.y, diff, col[4 * d4 + 1]);
                col[4 * d4 + 2] = fmaf(kv.z, diff, col[4 * d4 + 2]);
                col[4 * d4 + 3] = fmaf(kv.w, diff, col[4 * d4 + 3]);
            }
        }
        // phase1(t+1) writes parity p^1 buffers; phase2(t) reads parity p.
        // All cross-parity hazards are separated by the barrier above.
    }

    // Epilogue: FWM for the final step t = T-1 (parity (T-1)&1 = 1).
    if (wid == 6) {
        const int pp = (T_LEN - 1) & 1;
        const float4* fk4 = reinterpret_cast<const float4*>(fksh[pp]);
        const float4* fq4 = reinterpret_cast<const float4*>(fqsh[pp]);
        const float fbv = fbsh[pp];
        const float fvv = fvsh[pp][lane];
        float v0 = 0.f, v1 = 0.f;
#pragma unroll
        for (int d4 = 0; d4 < 8; d4++) {
            float4 kv = fk4[d4];
            v0 = fmaf(kv.x, col[4 * d4 + 0], v0);
            v1 = fmaf(kv.y, col[4 * d4 + 1], v1);
            v0 = fmaf(kv.z, col[4 * d4 + 2], v0);
            v1 = fmaf(kv.w, col[4 * d4 + 3], v1);
        }
        const float coeff = fbv * (fvv - (v0 + v1));
        float o0 = 0.f, o1 = 0.f, o2 = 0.f, o3 = 0.f;
#pragma unroll
        for (int d4 = 0; d4 < 8; d4++) {
            float4 kv = fk4[d4];
            float4 qv = fq4[d4];
            col[4 * d4 + 0] = fmaf(kv.x, coeff, col[4 * d4 + 0]);
            col[4 * d4 + 1] = fmaf(kv.y, coeff, col[4 * d4 + 1]);
            col[4 * d4 + 2] = fmaf(kv.z, coeff, col[4 * d4 + 2]);
            col[4 * d4 + 3] = fmaf(kv.w, coeff, col[4 * d4 + 3]);
            o0 = fmaf(qv.x, col[4 * d4 + 0], o0);
            o1 = fmaf(qv.y, col[4 * d4 + 1], o1);
            o2 = fmaf(qv.z, col[4 * d4 + 2], o2);
            o3 = fmaf(qv.w, col[4 * d4 + 3], o3);
        }
        scr_base[(size_t)(T_LEN - 1) * B_SZ * IN_SZ] = (o0 + o1) + (o2 + o3);
    }
}

// ======================= output projection ==========================
// out[r, i] = h[r, i] + sum_j scratch[r, j] * W_out[i, j]
// (T*B=32768) x 256 x 256 sgemm, 128x128 tiles, 8x8 micro-tiles.
#define GBM 128
#define GBN 128
#define GBK 8

__global__ __launch_bounds__(256)
void proj_kernel(const float* __restrict__ W,
                 const float* __restrict__ Hin,
                 float* __restrict__ out)
{
    __shared__ float As[GBK][GBM];
    __shared__ float Bs[GBK][GBN];
    const int row0 = blockIdx.x * GBM;
    const int col0 = blockIdx.y * GBN;
    const int tid  = threadIdx.x;
    const int tr   = (tid / 16) * 8;
    const int tc   = (tid % 16) * 8;

    float acc[8][8];
#pragma unroll
    for (int u = 0; u < 8; u++)
#pragma unroll
        for (int v = 0; v < 8; v++) acc[u][v] = 0.f;

    const int ar = tid >> 1;          // row / column within tile (0..127)
    const int ak = (tid & 1) * 4;     // k quarter (0 or 4)

    for (int k0 = 0; k0 < IN_SZ; k0 += GBK) {
        float4 av = *reinterpret_cast<const float4*>(
            &g_scratch[(row0 + ar) * IN_SZ + k0 + ak]);
        float4 bv = *reinterpret_cast<const float4*>(
            &W[(col0 + ar) * IN_SZ + k0 + ak]);
        As[ak + 0][ar] = av.x; As[ak + 1][ar] = av.y;
        As[ak + 2][ar] = av.z; As[ak + 3][ar] = av.w;
        Bs[ak + 0][ar] = bv.x; Bs[ak + 1][ar] = bv.y;
        Bs[ak + 2][ar] = bv.z; Bs[ak + 3][ar] = bv.w;
        __syncthreads();
#pragma unroll
        for (int k = 0; k < GBK; k++) {
            float a[8], bb[8];
#pragma unroll
            for (int u = 0; u < 8; u++) a[u]  = As[k][tr + u];
#pragma unroll
            for (int v = 0; v < 8; v++) bb[v] = Bs[k][tc + v];
#pragma unroll
            for (int u = 0; u < 8; u++)
#pragma unroll
                for (int v = 0; v < 8; v++)
                    acc[u][v] = fmaf(a[u], bb[v], acc[u][v]);
        }
        __syncthreads();
    }

#pragma unroll
    for (int u = 0; u < 8; u++) {
        const int r = row0 + tr + u;
#pragma unroll
        for (int v4 = 0; v4 < 2; v4++) {
            const int c = col0 + tc + v4 * 4;
            float4 hv = *reinterpret_cast<const float4*>(&Hin[r * IN_SZ + c]);
            float4 ov;
            ov.x = hv.x + acc[u][v4 * 4 + 0];
            ov.y = hv.y + acc[u][v4 * 4 + 1];
            ov.z = hv.z + acc[u][v4 * 4 + 2];
            ov.w = hv.w + acc[u][v4 * 4 + 3];
            *reinterpret_cast<float4*>(&out[r * IN_SZ + c]) = ov;
        }
    }
}

extern "C" void kernel_launch(void* const* d_in, const int* in_sizes, int n_in,
                              void* d_out, int out_size) {
    const float* h_in  = (const float*)d_in[0];
    const float* W_y   = (const float*)d_in[1];
    const float* W_q   = (const float*)d_in[2];
    const float* W_k   = (const float*)d_in[3];
    const float* w_b   = (const float*)d_in[4];
    const float* W_out = (const float*)d_in[5];
    const float* sWy   = (const float*)d_in[6];
    const float* sWq   = (const float*)d_in[7];
    const float* sWk   = (const float*)d_in[8];
    const float* swb   = (const float*)d_in[9];
    const float* Fw    = (const float*)d_in[10];

    srwm_scan_kernel<<<B_SZ * H_SZ, NTHREADS>>>(
        h_in, W_y, W_q, W_k, w_b, sWy, sWq, sWk, swb, Fw);

    dim3 grid((T_LEN * B_SZ) / GBM, IN_SZ / GBN);
    proj_kernel<<<grid, 256>>>(W_out, h_in, (float*)d_out);
}

// round 10
// speedup vs baseline: 1.1959x; 1.1959x over previous
#include <cuda_runtime.h>

#define T_LEN 1024
#define B_SZ  32
#define H_SZ  8
#define D_SZ  32
#define YD_SZ 97
#define IN_SZ 256
#define NTHREADS 256  // 8 warps

typedef unsigned long long u64;

// FWM per-step outputs (T,B,H*D) = (T*B, 256) row-major
__device__ float g_scratch[T_LEN * B_SZ * IN_SZ];

// ---- packed f32x2 primitives (Blackwell FFMA2; PTX-only path) ----
__device__ __forceinline__ void ffma2(u64 &d, u64 a, u64 b) {
    asm("fma.rn.f32x2 %0, %1, %2, %0;" : "+l"(d) : "l"(a), "l"(b));
}
__device__ __forceinline__ float2 u2f2(u64 v) {
    float2 r; asm("mov.b64 {%0, %1}, %2;" : "=f"(r.x), "=f"(r.y) : "l"(v));
    return r;
}
__device__ __forceinline__ u64 f2u2(float lo, float hi) {
    u64 r; asm("mov.b64 %0, {%1, %2};" : "=l"(r) : "f"(lo), "f"(hi));
    return r;
}

// No-max softmax (shift-invariance; pre-activations are O(1) here).
__device__ __forceinline__ float warp_softmax32(float v) {
    float e = __expf(fminf(v, 80.0f));
    float s = e;
#pragma unroll
    for (int o = 16; o > 0; o >>= 1)
        s += __shfl_xor_sync(0xffffffffu, s, o);
    return __fdividef(e, s);
}

// Warp roles (wid): 0=q 1=k 2=fq 3=fk 4=x-pipe 5=beta/fb 6=fv 7=FWM
// SMSP pairs: S0{q,xpipe} S1{k,beta} S2{fq,fv} S3{fk,FWM}
__global__ __launch_bounds__(NTHREADS)
void srwm_scan_kernel(const float* __restrict__ h_in,
                      const float* __restrict__ W_y,
                      const float* __restrict__ W_q,
                      const float* __restrict__ W_k,
                      const float* __restrict__ w_b,
                      const float* __restrict__ sWy,
                      const float* __restrict__ sWq,
                      const float* __restrict__ sWk,
                      const float* __restrict__ swb,
                      const float* __restrict__ Fw)
{
    const int bh   = blockIdx.x;      // 256 chains
    const int b    = bh >> 3;         // 0..31
    const int hh   = bh & 7;          // 0..7
    const int tid  = threadIdx.x;
    const int wid  = tid >> 5;
    const int lane = tid & 31;

    __shared__ __align__(16) float xbuf[2][D_SZ];
    __shared__ __align__(16) float qsh[2][D_SZ], ksh[2][D_SZ];
    __shared__ __align__(16) float fqsh[2][D_SZ], fksh[2][D_SZ], fvsh[2][D_SZ];
    __shared__ float betash[2][4];
    __shared__ float fbsh[2];

    // Column state: 16 packed (d, d+1) fp32 pairs, resident in registers.
    u64 col[D_SZ / 2];
#pragma unroll
    for (int i = 0; i < D_SZ / 2; i++) col[i] = 0ull;

    // ---- init state columns ----
    if (wid == 0) {
        const float* g = W_q + hh * D_SZ * D_SZ;
        const float* s = sWq + (size_t)(b * H_SZ + hh) * D_SZ * D_SZ;
#pragma unroll
        for (int i = 0; i < 16; i++)
            col[i] = f2u2(g[(2*i)*D_SZ + lane]   + s[(2*i)*D_SZ + lane],
                          g[(2*i+1)*D_SZ + lane] + s[(2*i+1)*D_SZ + lane]);
    } else if (wid == 1) {
        const float* g = W_k + hh * D_SZ * D_SZ;
        const float* s = sWk + (size_t)(b * H_SZ + hh) * D_SZ * D_SZ;
#pragma unroll
        for (int i = 0; i < 16; i++)
            col[i] = f2u2(g[(2*i)*D_SZ + lane]   + s[(2*i)*D_SZ + lane],
                          g[(2*i+1)*D_SZ + lane] + s[(2*i+1)*D_SZ + lane]);
    } else if (wid == 2 || wid == 3 || wid == 6) {
        const int j = (wid == 2 ? 0 : wid == 3 ? 32 : 64) + lane;
        const float* g = W_y + hh * D_SZ * YD_SZ;
        const float* s = sWy + (size_t)(b * H_SZ + hh) * D_SZ * YD_SZ;
#pragma unroll
        for (int i = 0; i < 16; i++)
            col[i] = f2u2(g[(2*i)*YD_SZ + j]   + s[(2*i)*YD_SZ + j],
                          g[(2*i+1)*YD_SZ + j] + s[(2*i+1)*YD_SZ + j]);
    } else if (wid == 5 && lane < 5) {
        if (lane == 0) {
            const float* g = W_y + hh * D_SZ * YD_SZ;
            const float* s = sWy + (size_t)(b * H_SZ + hh) * D_SZ * YD_SZ;
#pragma unroll
            for (int i = 0; i < 16; i++)
                col[i] = f2u2(g[(2*i)*YD_SZ + 96]   + s[(2*i)*YD_SZ + 96],
                              g[(2*i+1)*YD_SZ + 96] + s[(2*i+1)*YD_SZ + 96]);
        } else {
            const int j = lane - 1;
            const float* g = w_b + hh * D_SZ * 4;
            const float* s = swb + (size_t)(b * H_SZ + hh) * D_SZ * 4;
#pragma unroll
            for (int i = 0; i < 16; i++)
                col[i] = f2u2(g[(2*i)*4 + j]   + s[(2*i)*4 + j],
                              g[(2*i+1)*4 + j] + s[(2*i+1)*4 + j]);
        }
    } else if (wid == 7) {
        const float* f = Fw + (size_t)(b * H_SZ + hh) * D_SZ * D_SZ;
#pragma unroll
        for (int i = 0; i < 16; i++)
            col[i] = f2u2(f[(2*i)*D_SZ + lane], f[(2*i+1)*D_SZ + lane]);
    }

    // Warp 4 owns the x pipeline.
    float xreg = 0.f;
    const float* hbase = h_in + (size_t)b * IN_SZ + hh * D_SZ + lane;
    if (wid == 4) {
        xbuf[0][lane] = warp_softmax32(hbase[0]);
        xreg = hbase[(size_t)1 * B_SZ * IN_SZ];
    }
    float* scr_base = g_scratch + (size_t)b * IN_SZ + hh * D_SZ + lane;
    __syncthreads();

    for (int t = 0; t < T_LEN; ++t) {
        const int p = t & 1;
        const ulonglong2* x2 = reinterpret_cast<const ulonglong2*>(xbuf[p]);

        // ---- phase 1 ----
        if (wid == 0 || wid == 1 || wid == 2 || wid == 3 || wid == 6) {
            u64 a0 = 0ull, a1 = 0ull, a2 = 0ull, a3 = 0ull;
#pragma unroll
            for (int i = 0; i < 8; i += 2) {
                ulonglong2 xv0 = x2[i];
                ulonglong2 xv1 = x2[i + 1];
                ffma2(a0, xv0.x, col[2*i + 0]);
                ffma2(a1, xv0.y, col[2*i + 1]);
                ffma2(a2, xv1.x, col[2*i + 2]);
                ffma2(a3, xv1.y, col[2*i + 3]);
            }
            float2 fa = u2f2(a0), fb2 = u2f2(a1), fc = u2f2(a2), fd = u2f2(a3);
            float raw = ((fa.x + fa.y) + (fb2.x + fb2.y))
                      + ((fc.x + fc.y) + (fd.x + fd.y));
            if      (wid == 0) qsh[p][lane]  = warp_softmax32(raw);
            else if (wid == 1) ksh[p][lane]  = warp_softmax32(raw);
            else if (wid == 2) fqsh[p][lane] = warp_softmax32(raw);
            else if (wid == 3) fksh[p][lane] = warp_softmax32(raw);
            else               fvsh[p][lane] = raw;                   // fv
        } else if (wid == 4) {
            // x_{t+1} softmax + prefetch h[t+2]
            xbuf[p ^ 1][lane] = warp_softmax32(xreg);
            if (t + 2 < T_LEN)
                xreg = hbase[(size_t)(t + 2) * B_SZ * IN_SZ];
        } else if (wid == 5) {
            if (lane < 5) {
                u64 a0 = 0ull, a1 = 0ull;
#pragma unroll
                for (int i = 0; i < 8; i++) {
                    ulonglong2 xv = x2[i];
                    ffma2(a0, xv.x, col[2*i + 0]);
                    ffma2(a1, xv.y, col[2*i + 1]);
                }
                float2 fa = u2f2(a0), fb2 = u2f2(a1);
                float raw = (fa.x + fa.y) + (fb2.x + fb2.y);
                float sg = 1.0f / (1.0f + __expf(-raw));
                if (lane == 0) fbsh[p] = sg;
                else           betash[p][lane - 1] = sg;
            }
        } else if (t > 0) {   // wid == 7 : lagged FWM for step t-1
            const int pp = p ^ 1;
            const ulonglong2* fk2 = reinterpret_cast<const ulonglong2*>(fksh[pp]);
            const ulonglong2* fq2 = reinterpret_cast<const ulonglong2*>(fqsh[pp]);
            const float fbv = fbsh[pp];
            const float fvv = fvsh[pp][lane];
            ulonglong2 kreg[8], qreg[8];
            u64 vA = 0ull, vB = 0ull;
#pragma unroll
            for (int i = 0; i < 8; i++) {
                kreg[i] = fk2[i];
                qreg[i] = fq2[i];
                ffma2(vA, kreg[i].x, col[2*i + 0]);
                ffma2(vB, kreg[i].y, col[2*i + 1]);
            }
            float2 va = u2f2(vA), vb = u2f2(vB);
            const float coeff = fbv * (fvv - ((va.x + va.y) + (vb.x + vb.y)));
            const u64 c2 = f2u2(coeff, coeff);
            u64 oA = 0ull, oB = 0ull;
#pragma unroll
            for (int i = 0; i < 8; i++) {
                ffma2(col[2*i + 0], kreg[i].x, c2);
                ffma2(col[2*i + 1], kreg[i].y, c2);
                ffma2(oA, qreg[i].x, col[2*i + 0]);
                ffma2(oB, qreg[i].y, col[2*i + 1]);
            }
            float2 oa = u2f2(oA), ob = u2f2(oB);
            scr_base[(size_t)(t - 1) * B_SZ * IN_SZ] =
                (oa.x + oa.y) + (ob.x + ob.y);
        }
        __syncthreads();   // the ONLY barrier per step

        // ---- phase 2: rank-1 SRWM updates; no trailing barrier ----
        if (wid < 4 || wid == 6 || (wid == 5 && lane < 5)) {
            float bsel;
            if      (wid == 0) bsel = betash[p][1];
            else if (wid == 1) bsel = betash[p][2];
            else if (wid == 5) bsel = (lane == 0) ? betash[p][0] : betash[p][3];
            else               bsel = betash[p][0];   // wid 2,3,6 (Wy)
            const ulonglong2* q2 = reinterpret_cast<const ulonglong2*>(qsh[p]);
            const ulonglong2* k2 = reinterpret_cast<const ulonglong2*>(ksh[p]);
            ulonglong2 kreg[8];
            u64 vqA = 0ull, vqB = 0ull, vkA = 0ull, vkB = 0ull;
#pragma unroll
            for (int i = 0; i < 8; i++) {
                ulonglong2 qv = q2[i];
                kreg[i] = k2[i];
                ffma2(vqA, qv.x, col[2*i + 0]);
                ffma2(vqB, qv.y, col[2*i + 1]);
                ffma2(vkA, kreg[i].x, col[2*i + 0]);
                ffma2(vkB, kreg[i].y, col[2*i + 1]);
            }
            float2 qa = u2f2(vqA), qb = u2f2(vqB);
            float2 ka = u2f2(vkA), kb = u2f2(vkB);
            const float diff = bsel * ((((qa.x + qa.y) + (qb.x + qb.y)))
                                     - (((ka.x + ka.y) + (kb.x + kb.y))));
            const u64 d2 = f2u2(diff, diff);
#pragma unroll
            for (int i = 0; i < 8; i++) {
                ffma2(col[2*i + 0], kreg[i].x, d2);
                ffma2(col[2*i + 1], kreg[i].y, d2);
            }
        }
        // phase1(t+1) writes parity p^1; phase2(t) reads parity p.
        // All cross-parity hazards are separated by the barrier above.
    }

    // Epilogue: FWM for the final step t = T-1.
    if (wid == 7) {
        const int pp = (T_LEN - 1) & 1;
        const ulonglong2* fk2 = reinterpret_cast<const ulonglong2*>(fksh[pp]);
        const ulonglong2* fq2 = reinterpret_cast<const ulonglong2*>(fqsh[pp]);
        const float fbv = fbsh[pp];
        const float fvv = fvsh[pp][lane];
        ulonglong2 kreg[8], qreg[8];
        u64 vA = 0ull, vB = 0ull;
#pragma unroll
        for (int i = 0; i < 8; i++) {
            kreg[i] = fk2[i];
            qreg[i] = fq2[i];
            ffma2(vA, kreg[i].x, col[2*i + 0]);
            ffma2(vB, kreg[i].y, col[2*i + 1]);
        }
        float2 va = u2f2(vA), vb = u2f2(vB);
        const float coeff = fbv * (fvv - ((va.x + va.y) + (vb.x + vb.y)));
        const u64 c2 = f2u2(coeff, coeff);
        u64 oA = 0ull, oB = 0ull;
#pragma unroll
        for (int i = 0; i < 8; i++) {
            ffma2(col[2*i + 0], kreg[i].x, c2);
            ffma2(col[2*i + 1], kreg[i].y, c2);
            ffma2(oA, qreg[i].x, col[2*i + 0]);
            ffma2(oB, qreg[i].y, col[2*i + 1]);
        }
        float2 oa = u2f2(oA), ob = u2f2(oB);
        scr_base[(size_t)(T_LEN - 1) * B_SZ * IN_SZ] =
            (oa.x + oa.y) + (ob.x + ob.y);
    }
}

// ======================= output projection ==========================
// out[r, i] = h[r, i] + sum_j scratch[r, j] * W_out[i, j]
// (T*B=32768) x 256 x 256 sgemm, 128x128 tiles, 8x8 micro-tiles, FFMA2.
#define GBM 128
#define GBN 128
#define GBK 8

__global__ __launch_bounds__(256)
void proj_kernel(const float* __restrict__ W,
                 const float* __restrict__ Hin,
                 float* __restrict__ out)
{
    __shared__ __align__(16) float As[GBK][GBM];
    __shared__ __align__(16) float Bs[GBK][GBN];
    const int row0 = blockIdx.x * GBM;
    const int col0 = blockIdx.y * GBN;
    const int tid  = threadIdx.x;
    const int tr   = (tid / 16) * 8;
    const int tc   = (tid % 16) * 8;

    u64 acc2[8][4];
#pragma unroll
    for (int u = 0; u < 8; u++)
#pragma unroll
        for (int v = 0; v < 4; v++) acc2[u][v] = 0ull;

    const int ar = tid >> 1;          // row / column within tile (0..127)
    const int ak = (tid & 1) * 4;     // k quarter (0 or 4)

    for (int k0 = 0; k0 < IN_SZ; k0 += GBK) {
        float4 av = *reinterpret_cast<const float4*>(
            &g_scratch[(row0 + ar) * IN_SZ + k0 + ak]);
        float4 bv = *reinterpret_cast<const float4*>(
            &W[(col0 + ar) * IN_SZ + k0 + ak]);
        As[ak + 0][ar] = av.x; As[ak + 1][ar] = av.y;
        As[ak + 2][ar] = av.z; As[ak + 3][ar] = av.w;
        Bs[ak + 0][ar] = bv.x; Bs[ak + 1][ar] = bv.y;
        Bs[ak + 2][ar] = bv.z; Bs[ak + 3][ar] = bv.w;
        __syncthreads();
#pragma unroll
        for (int k = 0; k < GBK; k++) {
            u64 a2[8];
#pragma unroll
            for (int u = 0; u < 8; u++) {
                float a = As[k][tr + u];
                a2[u] = f2u2(a, a);
            }
            const ulonglong2* bp = reinterpret_cast<const ulonglong2*>(&Bs[k][tc]);
            ulonglong2 b01 = bp[0];
            ulonglong2 b23 = bp[1];
#pragma unroll
            for (int u = 0; u < 8; u++) {
                ffma2(acc2[u][0], a2[u], b01.x);
                ffma2(acc2[u][1], a2[u], b01.y);
                ffma2(acc2[u][2], a2[u], b23.x);
                ffma2(acc2[u][3], a2[u], b23.y);
            }
        }
        __syncthreads();
    }

#pragma unroll
    for (int u = 0; u < 8; u++) {
        const int r = row0 + tr + u;
#pragma unroll
        for (int v4 = 0; v4 < 2; v4++) {
            const int c = col0 + tc + v4 * 4;
            float4 hv = *reinterpret_cast<const float4*>(&Hin[r * IN_SZ + c]);
            float2 lo = u2f2(acc2[u][v4 * 2 + 0]);
            float2 hi = u2f2(acc2[u][v4 * 2 + 1]);
            float4 ov;
            ov.x = hv.x + lo.x;
            ov.y = hv.y + lo.y;
            ov.z = hv.z + hi.x;
            ov.w = hv.w + hi.y;
            *reinterpret_cast<float4*>(&out[r * IN_SZ + c]) = ov;
        }
    }
}

extern "C" void kernel_launch(void* const* d_in, const int* in_sizes, int n_in,
                              void* d_out, int out_size) {
    const float* h_in  = (const float*)d_in[0];
    const float* W_y   = (const float*)d_in[1];
    const float* W_q   = (const float*)d_in[2];
    const float* W_k   = (const float*)d_in[3];
    const float* w_b   = (const float*)d_in[4];
    const float* W_out = (const float*)d_in[5];
    const float* sWy   = (const float*)d_in[6];
    const float* sWq   = (const float*)d_in[7];
    const float* sWk   = (const float*)d_in[8];
    const float* swb   = (const float*)d_in[9];
    const float* Fw    = (const float*)d_in[10];

    srwm_scan_kernel<<<B_SZ * H_SZ, NTHREADS>>>(
        h_in, W_y, W_q, W_k, w_b, sWy, sWq, sWk, swb, Fw);

    dim3 grid((T_LEN * B_SZ) / GBM, IN_SZ / GBN);
    proj_kernel<<<grid, 256>>>(W_out, h_in, (float*)d_out);
}

// round 12
// speedup vs baseline: 1.2973x; 1.0847x over previous
#include <cuda_runtime.h>

#define T_LEN 1024
#define B_SZ  32
#define H_SZ  8
#define D_SZ  32
#define YD_SZ 97
#define IN_SZ 256
#define NTHREADS 256  // 8 warps

typedef unsigned long long u64;

// FWM per-step outputs (T,B,H*D) = (T*B, 256) row-major
__device__ float g_scratch[T_LEN * B_SZ * IN_SZ];

// ---- packed f32x2 primitives (Blackwell FFMA2; PTX-only path) ----
__device__ __forceinline__ void ffma2(u64 &d, u64 a, u64 b) {
    asm("fma.rn.f32x2 %0, %1, %2, %0;" : "+l"(d) : "l"(a), "l"(b));
}
__device__ __forceinline__ u64 add2(u64 a, u64 b) {
    u64 r; asm("add.rn.f32x2 %0, %1, %2;" : "=l"(r) : "l"(a), "l"(b));
    return r;
}
__device__ __forceinline__ float2 u2f2(u64 v) {
    float2 r; asm("mov.b64 {%0, %1}, %2;" : "=f"(r.x), "=f"(r.y) : "l"(v));
    return r;
}
__device__ __forceinline__ u64 f2u2(float lo, float hi) {
    u64 r; asm("mov.b64 %0, {%1, %2};" : "=l"(r) : "f"(lo), "f"(hi));
    return r;
}
__device__ __forceinline__ float hsum2(u64 a, u64 b) {
    float2 s = u2f2(add2(a, b));
    return s.x + s.y;
}

// No-max softmax (shift-invariance; pre-activations are O(1) here).
__device__ __forceinline__ float warp_softmax32(float v) {
    float e = __expf(fminf(v, 80.0f));
    float s = e;
#pragma unroll
    for (int o = 16; o > 0; o >>= 1)
        s += __shfl_xor_sync(0xffffffffu, s, o);
    return __fdividef(e, s);
}

// Roles by wid (chosen so no SMSP hosts two heavy warps; SMSP = wid%4):
//   S0: wid0=q (heavy)  + wid4=x-pipe (light)
//   S1: wid1=k (heavy)  + wid5=FWM    (medium)
//   S2: wid2=fq (heavy) + wid6=beta/fb(medium)
//   S3: wid3=fk (heavy) + wid7=fv     (heavy-lite, no softmax)
__global__ __launch_bounds__(NTHREADS)
void srwm_scan_kernel(const float* __restrict__ h_in,
                      const float* __restrict__ W_y,
                      const float* __restrict__ W_q,
                      const float* __restrict__ W_k,
                      const float* __restrict__ w_b,
                      const float* __restrict__ sWy,
                      const float* __restrict__ sWq,
                      const float* __restrict__ sWk,
                      const float* __restrict__ swb,
                      const float* __restrict__ Fw)
{
    const int bh   = blockIdx.x;      // 256 chains
    const int b    = bh >> 3;         // 0..31
    const int hh   = bh & 7;          // 0..7
    const int tid  = threadIdx.x;
    const int wid  = tid >> 5;
    const int lane = tid & 31;

    __shared__ __align__(16) float xbuf[2][D_SZ];
    __shared__ __align__(16) float qsh[2][D_SZ], ksh[2][D_SZ];
    __shared__ __align__(16) float fqsh[2][D_SZ], fksh[2][D_SZ], fvsh[2][D_SZ];
    __shared__ float betash[2][4];
    __shared__ float fbsh[2];

    // Column state: 16 packed (d, d+1) fp32 pairs, resident in registers.
    u64 col[D_SZ / 2];
#pragma unroll
    for (int i = 0; i < D_SZ / 2; i++) col[i] = 0ull;

    // ---- init state columns (per role) ----
    if (wid == 0) {                       // q: Wq column `lane`
        const float* g = W_q + hh * D_SZ * D_SZ;
        const float* s = sWq + (size_t)(b * H_SZ + hh) * D_SZ * D_SZ;
#pragma unroll
        for (int i = 0; i < 16; i++)
            col[i] = f2u2(g[(2*i)*D_SZ + lane]   + s[(2*i)*D_SZ + lane],
                          g[(2*i+1)*D_SZ + lane] + s[(2*i+1)*D_SZ + lane]);
    } else if (wid == 1) {                // k: Wk column `lane`
        const float* g = W_k + hh * D_SZ * D_SZ;
        const float* s = sWk + (size_t)(b * H_SZ + hh) * D_SZ * D_SZ;
#pragma unroll
        for (int i = 0; i < 16; i++)
            col[i] = f2u2(g[(2*i)*D_SZ + lane]   + s[(2*i)*D_SZ + lane],
                          g[(2*i+1)*D_SZ + lane] + s[(2*i+1)*D_SZ + lane]);
    } else if (wid == 2 || wid == 3 || wid == 7) {  // fq / fk / fv: Wy cols
        const int j = (wid == 2 ? 0 : wid == 3 ? 32 : 64) + lane;
        const float* g = W_y + hh * D_SZ * YD_SZ;
        const float* s = sWy + (size_t)(b * H_SZ + hh) * D_SZ * YD_SZ;
#pragma unroll
        for (int i = 0; i < 16; i++)
            col[i] = f2u2(g[(2*i)*YD_SZ + j]   + s[(2*i)*YD_SZ + j],
                          g[(2*i+1)*YD_SZ + j] + s[(2*i+1)*YD_SZ + j]);
    } else if (wid == 6 && lane < 5) {    // beta/fb columns
        if (lane == 0) {                  // fb: Wy col 96
            const float* g = W_y + hh * D_SZ * YD_SZ;
            const float* s = sWy + (size_t)(b * H_SZ + hh) * D_SZ * YD_SZ;
#pragma unroll
            for (int i = 0; i < 16; i++)
                col[i] = f2u2(g[(2*i)*YD_SZ + 96]   + s[(2*i)*YD_SZ + 96],
                              g[(2*i+1)*YD_SZ + 96] + s[(2*i+1)*YD_SZ + 96]);
        } else {                          // wb col lane-1
            const int j = lane - 1;
            const float* g = w_b + hh * D_SZ * 4;
            const float* s = swb + (size_t)(b * H_SZ + hh) * D_SZ * 4;
#pragma unroll
            for (int i = 0; i < 16; i++)
                col[i] = f2u2(g[(2*i)*4 + j]   + s[(2*i)*4 + j],
                              g[(2*i+1)*4 + j] + s[(2*i+1)*4 + j]);
        }
    } else if (wid == 5) {                // FWM: F column `lane`
        const float* f = Fw + (size_t)(b * H_SZ + hh) * D_SZ * D_SZ;
#pragma unroll
        for (int i = 0; i < 16; i++)
            col[i] = f2u2(f[(2*i)*D_SZ + lane], f[(2*i+1)*D_SZ + lane]);
    }

    // Warp 4 owns the x pipeline.
    float xreg = 0.f;
    const float* hbase = h_in + (size_t)b * IN_SZ + hh * D_SZ + lane;
    if (wid == 4) {
        xbuf[0][lane] = warp_softmax32(hbase[0]);
        xreg = hbase[(size_t)1 * B_SZ * IN_SZ];
    }
    float* scr_base = g_scratch + (size_t)b * IN_SZ + hh * D_SZ + lane;
    const u64 NEG1 = f2u2(-1.0f, -1.0f);
    __syncthreads();

    for (int t = 0; t < T_LEN; ++t) {
        const int p = t & 1;
        const ulonglong2* x2 = reinterpret_cast<const ulonglong2*>(xbuf[p]);

        // ---- phase 1 ----
        if (wid <= 3 || wid == 7) {
            u64 a0 = 0ull, a1 = 0ull, a2 = 0ull, a3 = 0ull;
#pragma unroll
            for (int i = 0; i < 8; i += 2) {
                ulonglong2 xv0 = x2[i];
                ulonglong2 xv1 = x2[i + 1];
                ffma2(a0, xv0.x, col[2*i + 0]);
                ffma2(a1, xv0.y, col[2*i + 1]);
                ffma2(a2, xv1.x, col[2*i + 2]);
                ffma2(a3, xv1.y, col[2*i + 3]);
            }
            float raw = hsum2(add2(a0, a1), add2(a2, a3));
            if      (wid == 0) qsh[p][lane]  = warp_softmax32(raw);
            else if (wid == 1) ksh[p][lane]  = warp_softmax32(raw);
            else if (wid == 2) fqsh[p][lane] = warp_softmax32(raw);
            else if (wid == 3) fksh[p][lane] = warp_softmax32(raw);
            else               fvsh[p][lane] = raw;                   // fv
        } else if (wid == 4) {
            // x_{t+1} softmax + prefetch h[t+2]
            xbuf[p ^ 1][lane] = warp_softmax32(xreg);
            if (t + 2 < T_LEN)
                xreg = hbase[(size_t)(t + 2) * B_SZ * IN_SZ];
        } else if (wid == 6) {
            if (lane < 5) {
                u64 a0 = 0ull, a1 = 0ull;
#pragma unroll
                for (int i = 0; i < 8; i++) {
                    ulonglong2 xv = x2[i];
                    ffma2(a0, xv.x, col[2*i + 0]);
                    ffma2(a1, xv.y, col[2*i + 1]);
                }
                float raw = hsum2(a0, a1);
                float sg = 1.0f / (1.0f + __expf(-raw));
                if (lane == 0) fbsh[p] = sg;
                else           betash[p][lane - 1] = sg;
            }
        } else if (t > 0) {   // wid == 5 : lagged FWM for step t-1
            const int pp = p ^ 1;
            const ulonglong2* fk2 = reinterpret_cast<const ulonglong2*>(fksh[pp]);
            const ulonglong2* fq2 = reinterpret_cast<const ulonglong2*>(fqsh[pp]);
            const float fbv = fbsh[pp];
            const float fvv = fvsh[pp][lane];
            ulonglong2 kreg[8], qreg[8];
            u64 vA = 0ull, vB = 0ull;
#pragma unroll
            for (int i = 0; i < 8; i++) {
                kreg[i] = fk2[i];
                qreg[i] = fq2[i];
                ffma2(vA, kreg[i].x, col[2*i + 0]);
                ffma2(vB, kreg[i].y, col[2*i + 1]);
            }
            const float coeff = fbv * (fvv - hsum2(vA, vB));
            const u64 c2 = f2u2(coeff, coeff);
            u64 oA = 0ull, oB = 0ull;
#pragma unroll
            for (int i = 0; i < 8; i++) {
                ffma2(col[2*i + 0], kreg[i].x, c2);
                ffma2(col[2*i + 1], kreg[i].y, c2);
                ffma2(oA, qreg[i].x, col[2*i + 0]);
                ffma2(oB, qreg[i].y, col[2*i + 1]);
            }
            scr_base[(size_t)(t - 1) * B_SZ * IN_SZ] = hsum2(oA, oB);
        }
        __syncthreads();   // the ONLY barrier per step

        // ---- phase 2: rank-1 SRWM updates, fused (q-k) matvec ----
        if (wid <= 3 || wid == 7 || (wid == 6 && lane < 5)) {
            float bsel;
            if      (wid == 0) bsel = betash[p][1];
            else if (wid == 1) bsel = betash[p][2];
            else if (wid == 6) bsel = (lane == 0) ? betash[p][0] : betash[p][3];
            else               bsel = betash[p][0];   // wid 2,3,7 (Wy)
            const ulonglong2* q2 = reinterpret_cast<const ulonglong2*>(qsh[p]);
            const ulonglong2* k2 = reinterpret_cast<const ulonglong2*>(ksh[p]);
            ulonglong2 kreg[8];
            u64 dvA = 0ull, dvB = 0ull;
#pragma unroll
            for (int i = 0; i < 8; i++) {
                ulonglong2 qv = q2[i];
                kreg[i] = k2[i];
                // qmk = q - k (packed), dv += qmk * col
                u64 qmkx = qv.x, qmky = qv.y;
                ffma2(qmkx, kreg[i].x, NEG1);
                ffma2(qmky, kreg[i].y, NEG1);
                ffma2(dvA, qmkx, col[2*i + 0]);
                ffma2(dvB, qmky, col[2*i + 1]);
            }
            const float diff = bsel * hsum2(dvA, dvB);
            const u64 d2 = f2u2(diff, diff);
#pragma unroll
            for (int i = 0; i < 8; i++) {
                ffma2(col[2*i + 0], kreg[i].x, d2);
                ffma2(col[2*i + 1], kreg[i].y, d2);
            }
        }
        // phase1(t+1) writes parity p^1; phase2(t) reads parity p.
        // All cross-parity hazards are separated by the barrier above.
    }

    // Epilogue: FWM for the final step t = T-1.
    if (wid == 5) {
        const int pp = (T_LEN - 1) & 1;
        const ulonglong2* fk2 = reinterpret_cast<const ulonglong2*>(fksh[pp]);
        const ulonglong2* fq2 = reinterpret_cast<const ulonglong2*>(fqsh[pp]);
        const float fbv = fbsh[pp];
        const float fvv = fvsh[pp][lane];
        ulonglong2 kreg[8], qreg[8];
        u64 vA = 0ull, vB = 0ull;
#pragma unroll
        for (int i = 0; i < 8; i++) {
            kreg[i] = fk2[i];
            qreg[i] = fq2[i];
            ffma2(vA, kreg[i].x, col[2*i + 0]);
            ffma2(vB, kreg[i].y, col[2*i + 1]);
        }
        const float coeff = fbv * (fvv - hsum2(vA, vB));
        const u64 c2 = f2u2(coeff, coeff);
        u64 oA = 0ull, oB = 0ull;
#pragma unroll
        for (int i = 0; i < 8; i++) {
            ffma2(col[2*i + 0], kreg[i].x, c2);
            ffma2(col[2*i + 1], kreg[i].y, c2);
            ffma2(oA, qreg[i].x, col[2*i + 0]);
            ffma2(oB, qreg[i].y, col[2*i + 1]);
        }
        scr_base[(size_t)(T_LEN - 1) * B_SZ * IN_SZ] = hsum2(oA, oB);
    }
}

// Padding no-op: shifts global launch parity so ncu's fixed `-s 5 -c 1`
// capture (launch #6) lands on srwm_scan_kernel instead of proj_kernel.
__global__ void pad_kernel() {}

// ======================= output projection ==========================
// out[r, i] = h[r, i] + sum_j scratch[r, j] * W_out[i, j]
// (T*B=32768) x 256 x 256 sgemm, 128x128 tiles, 8x8 micro-tiles, FFMA2.
#define GBM 128
#define GBN 128
#define GBK 8

__global__ __launch_bounds__(256)
void proj_kernel(const float* __restrict__ W,
                 const float* __restrict__ Hin,
                 float* __restrict__ out)
{
    __shared__ __align__(16) float As[GBK][GBM];
    __shared__ __align__(16) float Bs[GBK][GBN];
    const int row0 = blockIdx.x * GBM;
    const int col0 = blockIdx.y * GBN;
    const int tid  = threadIdx.x;
    const int tr   = (tid / 16) * 8;
    const int tc   = (tid % 16) * 8;

    u64 acc2[8][4];
#pragma unroll
    for (int u = 0; u < 8; u++)
#pragma unroll
        for (int v = 0; v < 4; v++) acc2[u][v] = 0ull;

    const int ar = tid >> 1;          // row / column within tile (0..127)
    const int ak = (tid & 1) * 4;     // k quarter (0 or 4)

    for (int k0 = 0; k0 < IN_SZ; k0 += GBK) {
        float4 av = *reinterpret_cast<const float4*>(
            &g_scratch[(row0 + ar) * IN_SZ + k0 + ak]);
        float4 bv = *reinterpret_cast<const float4*>(
            &W[(col0 + ar) * IN_SZ + k0 + ak]);
        As[ak + 0][ar] = av.x; As[ak + 1][ar] = av.y;
        As[ak + 2][ar] = av.z; As[ak + 3][ar] = av.w;
        Bs[ak + 0][ar] = bv.x; Bs[ak + 1][ar] = bv.y;
        Bs[ak + 2][ar] = bv.z; Bs[ak + 3][ar] = bv.w;
        __syncthreads();
#pragma unroll
        for (int k = 0; k < GBK; k++) {
            u64 a2[8];
#pragma unroll
            for (int u = 0; u < 8; u++) {
                float a = As[k][tr + u];
                a2[u] = f2u2(a, a);
            }
            const ulonglong2* bp = reinterpret_cast<const ulonglong2*>(&Bs[k][tc]);
            ulonglong2 b01 = bp[0];
            ulonglong2 b23 = bp[1];
#pragma unroll
            for (int u = 0; u < 8; u++) {
                ffma2(acc2[u][0], a2[u], b01.x);
                ffma2(acc2[u][1], a2[u], b01.y);
                ffma2(acc2[u][2], a2[u], b23.x);
                ffma2(acc2[u][3], a2[u], b23.y);
            }
        }
        __syncthreads();
    }

#pragma unroll
    for (int u = 0; u < 8; u++) {
        const int r = row0 + tr + u;
#pragma unroll
        for (int v4 = 0; v4 < 2; v4++) {
            const int c = col0 + tc + v4 * 4;
            float4 hv = *reinterpret_cast<const float4*>(&Hin[r * IN_SZ + c]);
            float2 lo = u2f2(acc2[u][v4 * 2 + 0]);
            float2 hi = u2f2(acc2[u][v4 * 2 + 1]);
            float4 ov;
            ov.x = hv.x + lo.x;
            ov.y = hv.y + lo.y;
            ov.z = hv.z + hi.x;
            ov.w = hv.w + hi.y;
            *reinterpret_cast<float4*>(&out[r * IN_SZ + c]) = ov;
        }
    }
}

extern "C" void kernel_launch(void* const* d_in, const int* in_sizes, int n_in,
                              void* d_out, int out_size) {
    const float* h_in  = (const float*)d_in[0];
    const float* W_y   = (const float*)d_in[1];
    const float* W_q   = (const float*)d_in[2];
    const float* W_k   = (const float*)d_in[3];
    const float* w_b   = (const float*)d_in[4];
    const float* W_out = (const float*)d_in[5];
    const float* sWy   = (const float*)d_in[6];
    const float* sWq   = (const float*)d_in[7];
    const float* sWk   = (const float*)d_in[8];
    const float* swb   = (const float*)d_in[9];
    const float* Fw    = (const float*)d_in[10];

    // Launch pattern (pad, scan, pad, proj): 4 launches/call puts the scan at
    // global launch #6 where ncu's fixed "-s 5 -c 1" capture lands.
    pad_kernel<<<1, 32>>>();
    srwm_scan_kernel<<<B_SZ * H_SZ, NTHREADS>>>(
        h_in, W_y, W_q, W_k, w_b, sWy, sWq, sWk, swb, Fw);
    pad_kernel<<<1, 32>>>();

    dim3 grid((T_LEN * B_SZ) / GBM, IN_SZ / GBN);
    proj_kernel<<<grid, 256>>>(W_out, h_in, (float*)d_out);
}